// round 14
// baseline (speedup 1.0000x reference)
#include <cuda_runtime.h>
#include <cuda_fp16.h>
#include <cstdint>

#define N_NODES 50000
#define N_EDGES 600000
#define DH 128
#define SCAN_BLOCKS ((N_NODES + 1023) / 1024)   // 49
#define NTILES ((N_NODES + 63) / 64)            // 782

// ---------------- device scratch ----------------
__device__ __half g_F16[N_NODES * DH];   // fp16 map (features, h1, then y3)
__device__ __half g_A16[N_NODES * DH];   // aggregated features (GEMM A input)
__device__ int   g_deg[N_NODES];         // ZERO invariant: re-zeroed by scanAC
__device__ int   g_row_ptr[N_NODES + 1];
__device__ int   g_col[N_EDGES];
__device__ int   g_slot[N_EDGES];
__device__ float g_inv_deg[N_NODES];
__device__ int   g_bsum[64];
__device__ int   g_ctr;                  // monotonic scan-barrier ticket counter
// weights pre-packed into mma.sync B-fragment order (fp16): [ks][nf][lane]
__device__ uint2 g_W1[8 * 16 * 32];
__device__ uint2 g_W2[8 * 16 * 32];
__device__ uint2 g_W3[8 * 8 * 32];

// ---------------- small helpers ----------------
__device__ __forceinline__ uint32_t smem_u32(const void* p) {
    uint32_t a;
    asm("{ .reg .u64 t; cvta.to.shared.u64 t, %1; cvt.u32.u64 %0, t; }" : "=r"(a) : "l"(p));
    return a;
}
__device__ __forceinline__ void ldmatrix_x4(uint32_t* r, uint32_t addr) {
    asm volatile("ldmatrix.sync.aligned.m8n8.x4.shared.b16 {%0,%1,%2,%3}, [%4];"
                 : "=r"(r[0]), "=r"(r[1]), "=r"(r[2]), "=r"(r[3]) : "r"(addr));
}
__device__ __forceinline__ void mma_f16(float* c, const uint32_t* a, const uint2 b) {
    asm volatile(
        "mma.sync.aligned.m16n8k16.row.col.f32.f16.f16.f32 "
        "{%0,%1,%2,%3},{%4,%5,%6,%7},{%8,%9},{%0,%1,%2,%3};"
        : "+f"(c[0]), "+f"(c[1]), "+f"(c[2]), "+f"(c[3])
        : "r"(a[0]), "r"(a[1]), "r"(a[2]), "r"(a[3]), "r"(b.x), "r"(b.y));
}
__device__ __forceinline__ unsigned pack_h2(float a, float b) {
    __half2 p = __floats2half2_rn(a, b);
    return *(unsigned*)&p;
}
// swizzled byte offset of fp16 col n in row r of a 64x128 fp16 tile (256B rows)
__device__ __forceinline__ int a_off(int r, int n) {
    return r * 256 + ((((n >> 3) ^ (r & 7))) << 4) + (n & 7) * 2;
}

// ---------------- weight prep piece (fp16 fragments) ----------------
__device__ __forceinline__ void prep_one(const float* W, uint2* outp, int N, int idx) {
    int lane = idx & 31;
    int nf = (idx >> 5) % (N / 8);
    int ks = (idx >> 5) / (N / 8);
    int k0 = ks * 16 + (lane & 3) * 2;
    int n = nf * 8 + (lane >> 2);
    float w0 = W[(k0 + 0) * N + n], w1 = W[(k0 + 1) * N + n];
    float w2 = W[(k0 + 8) * N + n], w3 = W[(k0 + 9) * N + n];
    outp[idx] = make_uint2(pack_h2(w0, w1), pack_h2(w2, w3));
}

// ---------------- combo: degree count + features->fp16 + weight prep ---------
#define E4B ((N_EDGES / 4 + 255) / 256)
#define CVT_CHUNKS (N_NODES * DH / 4)
#define CVTB2 1024
#define PREPB 40

__global__ void count_cvt_prep_kernel(const int* __restrict__ dst,
                                      const float* __restrict__ features,
                                      const float* __restrict__ W1,
                                      const float* __restrict__ W2,
                                      const float* __restrict__ W3) {
    if (blockIdx.x < E4B) {
        int i = blockIdx.x * blockDim.x + threadIdx.x;
        if (i < N_EDGES / 4) {
            int4 d = ((const int4*)dst)[i];
            int4 s;
            s.x = atomicAdd(&g_deg[d.x], 1);
            s.y = atomicAdd(&g_deg[d.y], 1);
            s.z = atomicAdd(&g_deg[d.z], 1);
            s.w = atomicAdd(&g_deg[d.w], 1);
            ((int4*)g_slot)[i] = s;
        }
    } else if (blockIdx.x < E4B + PREPB) {
        int idx = (blockIdx.x - E4B) * blockDim.x + threadIdx.x;
        const int T128 = 8 * 16 * 32;
        const int T64 = 8 * 8 * 32;
        if (idx < T128) prep_one(W1, g_W1, 128, idx);
        else if (idx < 2 * T128) prep_one(W2, g_W2, 128, idx - T128);
        else if (idx < 2 * T128 + T64) prep_one(W3, g_W3, 64, idx - 2 * T128);
    } else {
        // grid-stride fp16 convert (1024 blocks, ~6 float4 per thread)
        for (int idx = (blockIdx.x - E4B - PREPB) * blockDim.x + threadIdx.x;
             idx < CVT_CHUNKS; idx += CVTB2 * 256) {
            float4 v = ((const float4*)features)[idx];
            uint2 o;
            o.x = pack_h2(v.x, v.y);
            o.y = pack_h2(v.z, v.w);
            ((uint2*)g_F16)[idx] = o;
        }
    }
}

// ---------------- fused scan (49 blocks, global spin barrier) ----------------
__global__ void __launch_bounds__(1024) scanAC_kernel() {
    const int tid = threadIdx.x;
    const int lane = tid & 31, wid = tid >> 5;
    __shared__ int wtot[32];
    __shared__ int blockoff_s;

    int i = blockIdx.x * 1024 + tid;
    int d = (i < N_NODES) ? g_deg[i] : 0;
    if (i < N_NODES) g_deg[i] = 0;

    int x = d;
#pragma unroll
    for (int o = 1; o < 32; o <<= 1) {
        int y = __shfl_up_sync(~0u, x, o);
        if (lane >= o) x += y;
    }
    if (lane == 31) wtot[wid] = x;
    __syncthreads();

    if (wid == 0) {
        int v = wtot[lane];
        int orig = v;
#pragma unroll
        for (int o = 1; o < 32; o <<= 1) {
            int y = __shfl_up_sync(~0u, v, o);
            if (lane >= o) v += y;
        }
        int total = __shfl_sync(~0u, v, 31);
        wtot[lane] = v - orig;
        if (lane == 0) {
            g_bsum[blockIdx.x] = total;
            __threadfence();
            int ticket = atomicAdd(&g_ctr, 1);
            int target = (ticket / SCAN_BLOCKS) * SCAN_BLOCKS + SCAN_BLOCKS;
            while (*(volatile int*)&g_ctr < target) { }
            __threadfence();
        }
        __syncwarp();
        int bv = 0;
        if (lane < (int)blockIdx.x) bv = *(volatile int*)&g_bsum[lane];
        if (lane + 32 < (int)blockIdx.x) bv += *(volatile int*)&g_bsum[lane + 32];
#pragma unroll
        for (int o = 16; o > 0; o >>= 1) bv += __shfl_down_sync(~0u, bv, o);
        if (lane == 0) blockoff_s = bv;
    }
    __syncthreads();

    int excl = blockoff_s + wtot[wid] + (x - d);
    if (i < N_NODES) {
        g_row_ptr[i] = excl;
        g_inv_deg[i] = 1.0f / fmaxf((float)d, 1.0f);
    }
    if (blockIdx.x == 0 && tid == 0) g_row_ptr[N_NODES] = N_EDGES;
}

// ---------------- atomic-free CSR fill ----------------------------------------
__global__ void fill2_kernel(const int* __restrict__ src, const int* __restrict__ dst) {
    int i = blockIdx.x * blockDim.x + threadIdx.x;
    if (i < N_EDGES / 2) {
        int2 d = ((const int2*)dst)[i];
        int2 sl = ((const int2*)g_slot)[i];
        int2 s = ((const int2*)src)[i];
        g_col[__ldg(&g_row_ptr[d.x]) + sl.x] = s.x;
        g_col[__ldg(&g_row_ptr[d.y]) + sl.y] = s.y;
    }
}

// ---------------- aggregation (128-dim): vectorized col reads ----------------
__device__ __forceinline__ void agg_edge128(const __half* __restrict__ h, int s,
                                            int lane, float4& acc) {
    uint2 u = ((const uint2*)(h + (size_t)s * DH))[lane];
    float2 a = __half22float2(*(__half2*)&u.x), b = __half22float2(*(__half2*)&u.y);
    acc.x += a.x; acc.y += a.y; acc.z += b.x; acc.w += b.y;
}

__global__ void aggregate_f16_kernel(const __half* __restrict__ h,
                                     __half* __restrict__ outp) {
    const int node = (blockIdx.x * blockDim.x + threadIdx.x) >> 5;
    const int lane = threadIdx.x & 31;
    if (node >= N_NODES) return;

    const int start = g_row_ptr[node];
    const int end = g_row_ptr[node + 1];

    float4 acc = make_float4(0.f, 0.f, 0.f, 0.f);
    int t = start;
    // scalar head until 4-aligned
    while ((t & 3) && t < end) { agg_edge128(h, __ldg(&g_col[t]), lane, acc); t++; }
    // 8-edge body: two int4 col loads
    for (; t + 8 <= end; t += 8) {
        int4 c0 = *(const int4*)&g_col[t];
        int4 c1 = *(const int4*)&g_col[t + 4];
        uint2 u0 = ((const uint2*)(h + (size_t)c0.x * DH))[lane];
        uint2 u1 = ((const uint2*)(h + (size_t)c0.y * DH))[lane];
        uint2 u2 = ((const uint2*)(h + (size_t)c0.z * DH))[lane];
        uint2 u3 = ((const uint2*)(h + (size_t)c0.w * DH))[lane];
        uint2 u4 = ((const uint2*)(h + (size_t)c1.x * DH))[lane];
        uint2 u5 = ((const uint2*)(h + (size_t)c1.y * DH))[lane];
        uint2 u6 = ((const uint2*)(h + (size_t)c1.z * DH))[lane];
        uint2 u7 = ((const uint2*)(h + (size_t)c1.w * DH))[lane];
        __half2 a01 = __hadd2(*(__half2*)&u0.x, *(__half2*)&u1.x);
        __half2 a23 = __hadd2(*(__half2*)&u2.x, *(__half2*)&u3.x);
        __half2 a45 = __hadd2(*(__half2*)&u4.x, *(__half2*)&u5.x);
        __half2 a67 = __hadd2(*(__half2*)&u6.x, *(__half2*)&u7.x);
        __half2 b01 = __hadd2(*(__half2*)&u0.y, *(__half2*)&u1.y);
        __half2 b23 = __hadd2(*(__half2*)&u2.y, *(__half2*)&u3.y);
        __half2 b45 = __hadd2(*(__half2*)&u4.y, *(__half2*)&u5.y);
        __half2 b67 = __hadd2(*(__half2*)&u6.y, *(__half2*)&u7.y);
        __half2 a03 = __hadd2(a01, a23);
        __half2 a47 = __hadd2(a45, a67);
        __half2 b03 = __hadd2(b01, b23);
        __half2 b47 = __hadd2(b45, b67);
        float2 fa0 = __half22float2(a03), fa1 = __half22float2(a47);
        float2 fb0 = __half22float2(b03), fb1 = __half22float2(b47);
        acc.x += fa0.x + fa1.x;
        acc.y += fa0.y + fa1.y;
        acc.z += fb0.x + fb1.x;
        acc.w += fb0.y + fb1.y;
    }
    // 4-edge group
    if (t + 4 <= end) {
        int4 c0 = *(const int4*)&g_col[t];
        uint2 u0 = ((const uint2*)(h + (size_t)c0.x * DH))[lane];
        uint2 u1 = ((const uint2*)(h + (size_t)c0.y * DH))[lane];
        uint2 u2 = ((const uint2*)(h + (size_t)c0.z * DH))[lane];
        uint2 u3 = ((const uint2*)(h + (size_t)c0.w * DH))[lane];
        __half2 a01 = __hadd2(*(__half2*)&u0.x, *(__half2*)&u1.x);
        __half2 a23 = __hadd2(*(__half2*)&u2.x, *(__half2*)&u3.x);
        __half2 b01 = __hadd2(*(__half2*)&u0.y, *(__half2*)&u1.y);
        __half2 b23 = __hadd2(*(__half2*)&u2.y, *(__half2*)&u3.y);
        __half2 a03 = __hadd2(a01, a23);
        __half2 b03 = __hadd2(b01, b23);
        float2 fa = __half22float2(a03), fb = __half22float2(b03);
        acc.x += fa.x; acc.y += fa.y; acc.z += fb.x; acc.w += fb.y;
        t += 4;
    }
    // scalar tail
    while (t < end) { agg_edge128(h, __ldg(&g_col[t]), lane, acc); t++; }

    const float inv = g_inv_deg[node];
    uint2 o;
    o.x = pack_h2(acc.x * inv, acc.y * inv);
    o.y = pack_h2(acc.z * inv, acc.w * inv);
    ((uint2*)(outp + (size_t)node * DH))[lane] = o;
}

// ---------------- final aggregation (64-dim): vectorized col reads -----------
__global__ void aggregate64_kernel(const __half* __restrict__ h,
                                   const float* __restrict__ bias,
                                   float* __restrict__ out) {
    const int node = (blockIdx.x * blockDim.x + threadIdx.x) >> 5;
    const int lane = threadIdx.x & 31;
    if (node >= N_NODES) return;

    const int start = g_row_ptr[node];
    const int end = g_row_ptr[node + 1];

    float2 acc = make_float2(0.f, 0.f);
    int t = start;
    while ((t & 3) && t < end) {
        int s = __ldg(&g_col[t]);
        unsigned u = ((const unsigned*)(h + (size_t)s * 64))[lane];
        float2 f = __half22float2(*(__half2*)&u);
        acc.x += f.x; acc.y += f.y;
        t++;
    }
    for (; t + 8 <= end; t += 8) {
        int4 c0 = *(const int4*)&g_col[t];
        int4 c1 = *(const int4*)&g_col[t + 4];
        unsigned u0 = ((const unsigned*)(h + (size_t)c0.x * 64))[lane];
        unsigned u1 = ((const unsigned*)(h + (size_t)c0.y * 64))[lane];
        unsigned u2 = ((const unsigned*)(h + (size_t)c0.z * 64))[lane];
        unsigned u3 = ((const unsigned*)(h + (size_t)c0.w * 64))[lane];
        unsigned u4 = ((const unsigned*)(h + (size_t)c1.x * 64))[lane];
        unsigned u5 = ((const unsigned*)(h + (size_t)c1.y * 64))[lane];
        unsigned u6 = ((const unsigned*)(h + (size_t)c1.z * 64))[lane];
        unsigned u7 = ((const unsigned*)(h + (size_t)c1.w * 64))[lane];
        __half2 p01 = __hadd2(*(__half2*)&u0, *(__half2*)&u1);
        __half2 p23 = __hadd2(*(__half2*)&u2, *(__half2*)&u3);
        __half2 p45 = __hadd2(*(__half2*)&u4, *(__half2*)&u5);
        __half2 p67 = __hadd2(*(__half2*)&u6, *(__half2*)&u7);
        __half2 p03 = __hadd2(p01, p23);
        __half2 p47 = __hadd2(p45, p67);
        float2 f0 = __half22float2(p03), f1 = __half22float2(p47);
        acc.x += f0.x + f1.x;
        acc.y += f0.y + f1.y;
    }
    if (t + 4 <= end) {
        int4 c0 = *(const int4*)&g_col[t];
        unsigned u0 = ((const unsigned*)(h + (size_t)c0.x * 64))[lane];
        unsigned u1 = ((const unsigned*)(h + (size_t)c0.y * 64))[lane];
        unsigned u2 = ((const unsigned*)(h + (size_t)c0.z * 64))[lane];
        unsigned u3 = ((const unsigned*)(h + (size_t)c0.w * 64))[lane];
        __half2 p01 = __hadd2(*(__half2*)&u0, *(__half2*)&u1);
        __half2 p23 = __hadd2(*(__half2*)&u2, *(__half2*)&u3);
        __half2 p03 = __hadd2(p01, p23);
        float2 f = __half22float2(p03);
        acc.x += f.x; acc.y += f.y;
        t += 4;
    }
    while (t < end) {
        int s = __ldg(&g_col[t]);
        unsigned u = ((const unsigned*)(h + (size_t)s * 64))[lane];
        float2 f = __half22float2(*(__half2*)&u);
        acc.x += f.x; acc.y += f.y;
        t++;
    }
    const float inv = g_inv_deg[node];
    float2 b = ((const float2*)bias)[lane];
    acc.x = acc.x * inv + b.x;
    acc.y = acc.y * inv + b.y;
    ((float2*)(out + (size_t)node * 64))[lane] = acc;
}

// ---------------- persistent GEMM1: h1 = relu(A@W1+b1) -> fp16 ---------------
__global__ void __launch_bounds__(256, 3)
mma_gemm1(const __half* __restrict__ A, const uint2* __restrict__ B,
          const float* __restrict__ bias, __half* __restrict__ C16) {
    constexpr int BM = 64, BN = 128;
    constexpr int NF = 16, NFW = 8;
    constexpr int A_BYTES = BM * 256;
    constexpr int B_U2 = 8 * NF * 32;

    extern __shared__ __align__(1024) char sm[];
    uint2* Bs = (uint2*)(sm + A_BYTES);
    float* bias_s = (float*)(sm + A_BYTES + B_U2 * 8);

    const int tid = threadIdx.x;
    const uint32_t sb = smem_u32(sm);

    {
        uint4* d4 = (uint4*)Bs;
        const uint4* s4 = (const uint4*)B;
        for (int i = tid; i < B_U2 / 2; i += 256) d4[i] = s4[i];
        if (tid < BN) bias_s[tid] = bias[tid];
    }

    const int warp = tid >> 5, lane = tid & 31;
    const int wn = warp >> 2, wm = warp & 3;
    const int r = wm * 16 + (lane & 15);
    const int arow = r * 256;
    const int arx = r & 7;
    const int chi = lane >> 4;

    for (int mtile = blockIdx.x; mtile < NTILES; mtile += gridDim.x) {
        const int mblock = mtile * BM;
        __syncthreads();
        for (int i = tid; i < BM * 16; i += 256) {
            int row = i >> 4, c = i & 15;
            int grow = mblock + row;
            uint4 v = make_uint4(0, 0, 0, 0);
            if (grow < N_NODES) v = ((const uint4*)(A + (size_t)grow * 128))[c];
            *(uint4*)(sm + row * 256 + ((c ^ (row & 7)) << 4)) = v;
        }
        __syncthreads();

        float acc[NFW][4];
#pragma unroll
        for (int nf = 0; nf < NFW; nf++)
#pragma unroll
            for (int j = 0; j < 4; j++) acc[nf][j] = 0.f;

#pragma unroll
        for (int ks = 0; ks < 8; ks++) {
            uint32_t a[4];
            ldmatrix_x4(a, sb + arow + ((((ks << 1) | chi) ^ arx) << 4));
            uint2 b[NFW];
#pragma unroll
            for (int nf = 0; nf < NFW; nf++)
                b[nf] = Bs[(ks * NF + wn * NFW + nf) * 32 + lane];
#pragma unroll
            for (int nf = 0; nf < NFW; nf++) mma_f16(acc[nf], a, b[nf]);
        }

        const int row0 = mblock + wm * 16 + (lane >> 2);
#pragma unroll
        for (int nf = 0; nf < NFW; nf++) {
            int n0 = (wn * NFW + nf) * 8 + 2 * (lane & 3);
            float b0 = bias_s[n0], b1 = bias_s[n0 + 1];
            unsigned p0 = pack_h2(fmaxf(acc[nf][0] + b0, 0.f), fmaxf(acc[nf][1] + b1, 0.f));
            unsigned p1 = pack_h2(fmaxf(acc[nf][2] + b0, 0.f), fmaxf(acc[nf][3] + b1, 0.f));
            if (row0 < N_NODES)
                *(unsigned*)(C16 + (size_t)row0 * BN + n0) = p0;
            if (row0 + 8 < N_NODES)
                *(unsigned*)(C16 + (size_t)(row0 + 8) * BN + n0) = p1;
        }
    }
}

// ---------------- persistent fused GEMM2+GEMM3 (fp16 single-term) ------------
__global__ void __launch_bounds__(256, 3)
mma_gemm23(const __half* __restrict__ A,
           const uint2* __restrict__ B2, const uint2* __restrict__ B3,
           const float* __restrict__ bias2, __half* __restrict__ Y16) {
    constexpr int BM = 64;
    constexpr int A_BYTES = BM * 256;
    constexpr int B2_U2 = 8 * 16 * 32;
    constexpr int B3_U2 = 8 * 8 * 32;

    extern __shared__ __align__(1024) char sm[];
    uint2* Bs2 = (uint2*)(sm + A_BYTES);
    uint2* Bs3 = (uint2*)(sm + A_BYTES + B2_U2 * 8);
    float* bias_s = (float*)(sm + A_BYTES + B2_U2 * 8 + B3_U2 * 8);

    const int tid = threadIdx.x;
    const uint32_t sb = smem_u32(sm);

    {
        uint4* d2 = (uint4*)Bs2;
        const uint4* s2 = (const uint4*)B2;
        for (int i = tid; i < B2_U2 / 2; i += 256) d2[i] = s2[i];
        uint4* d3 = (uint4*)Bs3;
        const uint4* s3 = (const uint4*)B3;
        for (int i = tid; i < B3_U2 / 2; i += 256) d3[i] = s3[i];
        if (tid < 128) bias_s[tid] = bias2[tid];
    }

    const int warp = tid >> 5, lane = tid & 31;
    const int wn = warp >> 2, wm = warp & 3;
    const int r = wm * 16 + (lane & 15);
    const int arow = r * 256;
    const int arx = r & 7;
    const int chi = lane >> 4;
    const int lr0 = wm * 16 + (lane >> 2);

    for (int mtile = blockIdx.x; mtile < NTILES; mtile += gridDim.x) {
        const int mblock = mtile * BM;
        __syncthreads();
        for (int i = tid; i < BM * 16; i += 256) {
            int row = i >> 4, c = i & 15;
            int grow = mblock + row;
            uint4 v = make_uint4(0, 0, 0, 0);
            if (grow < N_NODES) v = ((const uint4*)(A + (size_t)grow * 128))[c];
            *(uint4*)(sm + row * 256 + ((c ^ (row & 7)) << 4)) = v;
        }
        __syncthreads();

        // ---- mainloop 1: A @ W2 ----
        float acc[8][4];
#pragma unroll
        for (int nf = 0; nf < 8; nf++)
#pragma unroll
            for (int j = 0; j < 4; j++) acc[nf][j] = 0.f;

#pragma unroll
        for (int ks = 0; ks < 8; ks++) {
            uint32_t a[4];
            ldmatrix_x4(a, sb + arow + ((((ks << 1) | chi) ^ arx) << 4));
            uint2 b[8];
#pragma unroll
            for (int nf = 0; nf < 8; nf++)
                b[nf] = Bs2[(ks * 16 + wn * 8 + nf) * 32 + lane];
#pragma unroll
            for (int nf = 0; nf < 8; nf++) mma_f16(acc[nf], a, b[nf]);
        }
        __syncthreads();  // all A reads done before overwrite

        // ---- h2 = relu(acc + b2) -> fp16 back into A smem ----
#pragma unroll
        for (int nf = 0; nf < 8; nf++) {
            int n0 = (wn * 8 + nf) * 8 + 2 * (lane & 3);
            float b0 = bias_s[n0], b1 = bias_s[n0 + 1];
            unsigned p0 = pack_h2(fmaxf(acc[nf][0] + b0, 0.f), fmaxf(acc[nf][1] + b1, 0.f));
            unsigned p1 = pack_h2(fmaxf(acc[nf][2] + b0, 0.f), fmaxf(acc[nf][3] + b1, 0.f));
            *(unsigned*)(sm + a_off(lr0, n0)) = p0;
            *(unsigned*)(sm + a_off(lr0 + 8, n0)) = p1;
        }
        __syncthreads();

        // ---- mainloop 2: h2 @ W3 (BN=64) ----
        float acc2[4][4];
#pragma unroll
        for (int nf = 0; nf < 4; nf++)
#pragma unroll
            for (int j = 0; j < 4; j++) acc2[nf][j] = 0.f;

#pragma unroll
        for (int ks = 0; ks < 8; ks++) {
            uint32_t a[4];
            ldmatrix_x4(a, sb + arow + ((((ks << 1) | chi) ^ arx) << 4));
            uint2 b[4];
#pragma unroll
            for (int nf = 0; nf < 4; nf++)
                b[nf] = Bs3[(ks * 8 + wn * 4 + nf) * 32 + lane];
#pragma unroll
            for (int nf = 0; nf < 4; nf++) mma_f16(acc2[nf], a, b[nf]);
        }

        const int row0 = mblock + lr0;
#pragma unroll
        for (int nf = 0; nf < 4; nf++) {
            int n0 = (wn * 4 + nf) * 8 + 2 * (lane & 3);
            unsigned p0 = pack_h2(acc2[nf][0], acc2[nf][1]);
            unsigned p1 = pack_h2(acc2[nf][2], acc2[nf][3]);
            if (row0 < N_NODES)
                *(unsigned*)(Y16 + (size_t)row0 * 64 + n0) = p0;
            if (row0 + 8 < N_NODES)
                *(unsigned*)(Y16 + (size_t)(row0 + 8) * 64 + n0) = p1;
        }
    }
}

// ---------------- launch ----------------
extern "C" void kernel_launch(void* const* d_in, const int* in_sizes, int n_in,
                              void* d_out, int out_size) {
    const float* features = (const float*)d_in[0];
    const int* src = (const int*)d_in[1];
    const int* dst = (const int*)d_in[2];
    const float* W1 = (const float*)d_in[3];
    const float* b1 = (const float*)d_in[4];
    const float* W2 = (const float*)d_in[5];
    const float* b2 = (const float*)d_in[6];
    const float* W3 = (const float*)d_in[7];
    const float* b3 = (const float*)d_in[8];
    float* out = (float*)d_out;

    void* p;
    cudaGetSymbolAddress(&p, g_F16); __half* F16 = (__half*)p;
    cudaGetSymbolAddress(&p, g_A16); __half* A16 = (__half*)p;
    cudaGetSymbolAddress(&p, g_W1); uint2* W1p = (uint2*)p;
    cudaGetSymbolAddress(&p, g_W2); uint2* W2p = (uint2*)p;
    cudaGetSymbolAddress(&p, g_W3); uint2* W3p = (uint2*)p;

    constexpr int SMEM1  = 64 * 256 + (8 * 16 * 32) * 8 + 512;                     // 49664
    constexpr int SMEM23 = 64 * 256 + (8 * 16 * 32) * 8 + (8 * 8 * 32) * 8 + 512;  // 66048
    cudaFuncSetAttribute(mma_gemm1,
                         cudaFuncAttributeMaxDynamicSharedMemorySize, SMEM1);
    cudaFuncSetAttribute(mma_gemm23,
                         cudaFuncAttributeMaxDynamicSharedMemorySize, SMEM23);

    const int AGG_BLOCKS = (N_NODES * 32 + 255) / 256;
    const int FILLB = (N_EDGES / 2 + 255) / 256;  // 1172

    // #1 degree count (+slot) + weight prep + features->fp16 (grid-stride cvt)
    count_cvt_prep_kernel<<<E4B + PREPB + CVTB2, 256>>>(dst, features, W1, W2, W3);
    // #2 fused scan (spin barrier) + deg re-zero
    scanAC_kernel<<<SCAN_BLOCKS, 1024>>>();
    // #3 atomic-free CSR fill
    fill2_kernel<<<FILLB, 256>>>(src, dst);

    // Layer 1 (#4 = profiled slot: aggregate)
    aggregate_f16_kernel<<<AGG_BLOCKS, 256>>>(F16, A16);
    mma_gemm1<<<148 * 3, 256, SMEM1>>>(A16, W1p, b1, F16);
    // Layer 2 + dense part of layer 3 (fused)
    aggregate_f16_kernel<<<AGG_BLOCKS, 256>>>(F16, A16);
    mma_gemm23<<<148 * 3, 256, SMEM23>>>(A16, W2p, W3p, b2, F16);
    // Layer 3 tail: aggregate + bias
    aggregate64_kernel<<<AGG_BLOCKS, 256>>>(F16, b3, out);
}

// round 15
// speedup vs baseline: 1.1130x; 1.1130x over previous
#include <cuda_runtime.h>
#include <cuda_fp16.h>
#include <cstdint>

#define N_NODES 50000
#define N_EDGES 600000
#define DH 128
#define SCAN_BLOCKS ((N_NODES + 1023) / 1024)   // 49
#define NTILES ((N_NODES + 63) / 64)            // 782

// ---------------- device scratch ----------------
__device__ __half g_F16[N_NODES * DH];   // fp16 map (features, h1, then y3)
__device__ __half g_A16[N_NODES * DH];   // aggregated features (GEMM A input)
__device__ int   g_deg[N_NODES];         // ZERO invariant: re-zeroed by scanAC
__device__ int   g_row_ptr[N_NODES + 1];
__device__ int   g_col[N_EDGES];
__device__ int   g_slot[N_EDGES];
__device__ float g_inv_deg[N_NODES];
__device__ int   g_bsum[64];
__device__ int   g_ctr;                  // monotonic scan-barrier ticket counter
// weights pre-packed into mma.sync B-fragment order (fp16): [ks][nf][lane]
__device__ uint2 g_W1[8 * 16 * 32];
__device__ uint2 g_W2[8 * 16 * 32];
__device__ uint2 g_W3[8 * 8 * 32];

// ---------------- small helpers ----------------
__device__ __forceinline__ uint32_t smem_u32(const void* p) {
    uint32_t a;
    asm("{ .reg .u64 t; cvta.to.shared.u64 t, %1; cvt.u32.u64 %0, t; }" : "=r"(a) : "l"(p));
    return a;
}
__device__ __forceinline__ void ldmatrix_x4(uint32_t* r, uint32_t addr) {
    asm volatile("ldmatrix.sync.aligned.m8n8.x4.shared.b16 {%0,%1,%2,%3}, [%4];"
                 : "=r"(r[0]), "=r"(r[1]), "=r"(r[2]), "=r"(r[3]) : "r"(addr));
}
__device__ __forceinline__ void mma_f16(float* c, const uint32_t* a, const uint2 b) {
    asm volatile(
        "mma.sync.aligned.m16n8k16.row.col.f32.f16.f16.f32 "
        "{%0,%1,%2,%3},{%4,%5,%6,%7},{%8,%9},{%0,%1,%2,%3};"
        : "+f"(c[0]), "+f"(c[1]), "+f"(c[2]), "+f"(c[3])
        : "r"(a[0]), "r"(a[1]), "r"(a[2]), "r"(a[3]), "r"(b.x), "r"(b.y));
}
__device__ __forceinline__ unsigned pack_h2(float a, float b) {
    __half2 p = __floats2half2_rn(a, b);
    return *(unsigned*)&p;
}
// swizzled byte offset of fp16 col n in row r of a 64x128 fp16 tile (256B rows)
__device__ __forceinline__ int a_off(int r, int n) {
    return r * 256 + ((((n >> 3) ^ (r & 7))) << 4) + (n & 7) * 2;
}

// ---------------- weight prep piece (fp16 fragments) ----------------
__device__ __forceinline__ void prep_one(const float* W, uint2* outp, int N, int idx) {
    int lane = idx & 31;
    int nf = (idx >> 5) % (N / 8);
    int ks = (idx >> 5) / (N / 8);
    int k0 = ks * 16 + (lane & 3) * 2;
    int n = nf * 8 + (lane >> 2);
    float w0 = W[(k0 + 0) * N + n], w1 = W[(k0 + 1) * N + n];
    float w2 = W[(k0 + 8) * N + n], w3 = W[(k0 + 9) * N + n];
    outp[idx] = make_uint2(pack_h2(w0, w1), pack_h2(w2, w3));
}

// ---------------- combo: degree count + features->fp16 + weight prep ---------
#define E4B ((N_EDGES / 4 + 255) / 256)
#define CVT_CHUNKS (N_NODES * DH / 4)
#define CVTB2 1024
#define PREPB 40

__global__ void count_cvt_prep_kernel(const int* __restrict__ dst,
                                      const float* __restrict__ features,
                                      const float* __restrict__ W1,
                                      const float* __restrict__ W2,
                                      const float* __restrict__ W3) {
    if (blockIdx.x < E4B) {
        int i = blockIdx.x * blockDim.x + threadIdx.x;
        if (i < N_EDGES / 4) {
            int4 d = ((const int4*)dst)[i];
            int4 s;
            s.x = atomicAdd(&g_deg[d.x], 1);
            s.y = atomicAdd(&g_deg[d.y], 1);
            s.z = atomicAdd(&g_deg[d.z], 1);
            s.w = atomicAdd(&g_deg[d.w], 1);
            ((int4*)g_slot)[i] = s;
        }
    } else if (blockIdx.x < E4B + PREPB) {
        int idx = (blockIdx.x - E4B) * blockDim.x + threadIdx.x;
        const int T128 = 8 * 16 * 32;
        const int T64 = 8 * 8 * 32;
        if (idx < T128) prep_one(W1, g_W1, 128, idx);
        else if (idx < 2 * T128) prep_one(W2, g_W2, 128, idx - T128);
        else if (idx < 2 * T128 + T64) prep_one(W3, g_W3, 64, idx - 2 * T128);
    } else {
        // grid-stride fp16 convert
        for (int idx = (blockIdx.x - E4B - PREPB) * blockDim.x + threadIdx.x;
             idx < CVT_CHUNKS; idx += CVTB2 * 256) {
            float4 v = ((const float4*)features)[idx];
            uint2 o;
            o.x = pack_h2(v.x, v.y);
            o.y = pack_h2(v.z, v.w);
            ((uint2*)g_F16)[idx] = o;
        }
    }
}

// ---------------- fused scan (49 blocks, global spin barrier) ----------------
__global__ void __launch_bounds__(1024) scanAC_kernel() {
    const int tid = threadIdx.x;
    const int lane = tid & 31, wid = tid >> 5;
    __shared__ int wtot[32];
    __shared__ int blockoff_s;

    int i = blockIdx.x * 1024 + tid;
    int d = (i < N_NODES) ? g_deg[i] : 0;
    if (i < N_NODES) g_deg[i] = 0;

    int x = d;
#pragma unroll
    for (int o = 1; o < 32; o <<= 1) {
        int y = __shfl_up_sync(~0u, x, o);
        if (lane >= o) x += y;
    }
    if (lane == 31) wtot[wid] = x;
    __syncthreads();

    if (wid == 0) {
        int v = wtot[lane];
        int orig = v;
#pragma unroll
        for (int o = 1; o < 32; o <<= 1) {
            int y = __shfl_up_sync(~0u, v, o);
            if (lane >= o) v += y;
        }
        int total = __shfl_sync(~0u, v, 31);
        wtot[lane] = v - orig;
        if (lane == 0) {
            g_bsum[blockIdx.x] = total;
            __threadfence();
            int ticket = atomicAdd(&g_ctr, 1);
            int target = (ticket / SCAN_BLOCKS) * SCAN_BLOCKS + SCAN_BLOCKS;
            while (*(volatile int*)&g_ctr < target) { }
            __threadfence();
        }
        __syncwarp();
        int bv = 0;
        if (lane < (int)blockIdx.x) bv = *(volatile int*)&g_bsum[lane];
        if (lane + 32 < (int)blockIdx.x) bv += *(volatile int*)&g_bsum[lane + 32];
#pragma unroll
        for (int o = 16; o > 0; o >>= 1) bv += __shfl_down_sync(~0u, bv, o);
        if (lane == 0) blockoff_s = bv;
    }
    __syncthreads();

    int excl = blockoff_s + wtot[wid] + (x - d);
    if (i < N_NODES) {
        g_row_ptr[i] = excl;
        g_inv_deg[i] = 1.0f / fmaxf((float)d, 1.0f);
    }
    if (blockIdx.x == 0 && tid == 0) g_row_ptr[N_NODES] = N_EDGES;
}

// ---------------- atomic-free CSR fill ----------------------------------------
__global__ void fill2_kernel(const int* __restrict__ src, const int* __restrict__ dst) {
    int i = blockIdx.x * blockDim.x + threadIdx.x;
    if (i < N_EDGES / 2) {
        int2 d = ((const int2*)dst)[i];
        int2 sl = ((const int2*)g_slot)[i];
        int2 s = ((const int2*)src)[i];
        g_col[__ldg(&g_row_ptr[d.x]) + sl.x] = s.x;
        g_col[__ldg(&g_row_ptr[d.y]) + sl.y] = s.y;
    }
}

// ---------------- aggregation (128-dim): 8-way unroll, 2-level fp16 tree -----
__global__ void aggregate_f16_kernel(const __half* __restrict__ h,
                                     __half* __restrict__ outp) {
    const int node = (blockIdx.x * blockDim.x + threadIdx.x) >> 5;
    const int lane = threadIdx.x & 31;
    if (node >= N_NODES) return;

    const int start = g_row_ptr[node];
    const int end = g_row_ptr[node + 1];

    float4 acc = make_float4(0.f, 0.f, 0.f, 0.f);
    int t = start;
    for (; t + 8 <= end; t += 8) {
        int s0 = __ldg(&g_col[t + 0]), s1 = __ldg(&g_col[t + 1]);
        int s2 = __ldg(&g_col[t + 2]), s3 = __ldg(&g_col[t + 3]);
        int s4 = __ldg(&g_col[t + 4]), s5 = __ldg(&g_col[t + 5]);
        int s6 = __ldg(&g_col[t + 6]), s7 = __ldg(&g_col[t + 7]);
        uint2 u0 = ((const uint2*)(h + (size_t)s0 * DH))[lane];
        uint2 u1 = ((const uint2*)(h + (size_t)s1 * DH))[lane];
        uint2 u2 = ((const uint2*)(h + (size_t)s2 * DH))[lane];
        uint2 u3 = ((const uint2*)(h + (size_t)s3 * DH))[lane];
        uint2 u4 = ((const uint2*)(h + (size_t)s4 * DH))[lane];
        uint2 u5 = ((const uint2*)(h + (size_t)s5 * DH))[lane];
        uint2 u6 = ((const uint2*)(h + (size_t)s6 * DH))[lane];
        uint2 u7 = ((const uint2*)(h + (size_t)s7 * DH))[lane];
        __half2 a01 = __hadd2(*(__half2*)&u0.x, *(__half2*)&u1.x);
        __half2 a23 = __hadd2(*(__half2*)&u2.x, *(__half2*)&u3.x);
        __half2 a45 = __hadd2(*(__half2*)&u4.x, *(__half2*)&u5.x);
        __half2 a67 = __hadd2(*(__half2*)&u6.x, *(__half2*)&u7.x);
        __half2 b01 = __hadd2(*(__half2*)&u0.y, *(__half2*)&u1.y);
        __half2 b23 = __hadd2(*(__half2*)&u2.y, *(__half2*)&u3.y);
        __half2 b45 = __hadd2(*(__half2*)&u4.y, *(__half2*)&u5.y);
        __half2 b67 = __hadd2(*(__half2*)&u6.y, *(__half2*)&u7.y);
        __half2 a03 = __hadd2(a01, a23);
        __half2 a47 = __hadd2(a45, a67);
        __half2 b03 = __hadd2(b01, b23);
        __half2 b47 = __hadd2(b45, b67);
        float2 fa0 = __half22float2(a03), fa1 = __half22float2(a47);
        float2 fb0 = __half22float2(b03), fb1 = __half22float2(b47);
        acc.x += fa0.x + fa1.x;
        acc.y += fa0.y + fa1.y;
        acc.z += fb0.x + fb1.x;
        acc.w += fb0.y + fb1.y;
    }
    for (; t + 2 <= end; t += 2) {
        int s0 = __ldg(&g_col[t + 0]);
        int s1 = __ldg(&g_col[t + 1]);
        uint2 u0 = ((const uint2*)(h + (size_t)s0 * DH))[lane];
        uint2 u1 = ((const uint2*)(h + (size_t)s1 * DH))[lane];
        __half2 a01 = __hadd2(*(__half2*)&u0.x, *(__half2*)&u1.x);
        __half2 b01 = __hadd2(*(__half2*)&u0.y, *(__half2*)&u1.y);
        float2 fa = __half22float2(a01), fb = __half22float2(b01);
        acc.x += fa.x; acc.y += fa.y; acc.z += fb.x; acc.w += fb.y;
    }
    if (t < end) {
        int s = __ldg(&g_col[t]);
        uint2 u = ((const uint2*)(h + (size_t)s * DH))[lane];
        float2 a = __half22float2(*(__half2*)&u.x), b = __half22float2(*(__half2*)&u.y);
        acc.x += a.x; acc.y += a.y; acc.z += b.x; acc.w += b.y;
    }
    const float inv = g_inv_deg[node];
    uint2 o;
    o.x = pack_h2(acc.x * inv, acc.y * inv);
    o.y = pack_h2(acc.z * inv, acc.w * inv);
    ((uint2*)(outp + (size_t)node * DH))[lane] = o;
}

// ---------------- final aggregation (64-dim): 8-way unroll, 2-level tree -----
__global__ void aggregate64_kernel(const __half* __restrict__ h,
                                   const float* __restrict__ bias,
                                   float* __restrict__ out) {
    const int node = (blockIdx.x * blockDim.x + threadIdx.x) >> 5;
    const int lane = threadIdx.x & 31;
    if (node >= N_NODES) return;

    const int start = g_row_ptr[node];
    const int end = g_row_ptr[node + 1];

    float2 acc = make_float2(0.f, 0.f);
    int t = start;
    for (; t + 8 <= end; t += 8) {
        int s0 = __ldg(&g_col[t + 0]), s1 = __ldg(&g_col[t + 1]);
        int s2 = __ldg(&g_col[t + 2]), s3 = __ldg(&g_col[t + 3]);
        int s4 = __ldg(&g_col[t + 4]), s5 = __ldg(&g_col[t + 5]);
        int s6 = __ldg(&g_col[t + 6]), s7 = __ldg(&g_col[t + 7]);
        unsigned u0 = ((const unsigned*)(h + (size_t)s0 * 64))[lane];
        unsigned u1 = ((const unsigned*)(h + (size_t)s1 * 64))[lane];
        unsigned u2 = ((const unsigned*)(h + (size_t)s2 * 64))[lane];
        unsigned u3 = ((const unsigned*)(h + (size_t)s3 * 64))[lane];
        unsigned u4 = ((const unsigned*)(h + (size_t)s4 * 64))[lane];
        unsigned u5 = ((const unsigned*)(h + (size_t)s5 * 64))[lane];
        unsigned u6 = ((const unsigned*)(h + (size_t)s6 * 64))[lane];
        unsigned u7 = ((const unsigned*)(h + (size_t)s7 * 64))[lane];
        __half2 p01 = __hadd2(*(__half2*)&u0, *(__half2*)&u1);
        __half2 p23 = __hadd2(*(__half2*)&u2, *(__half2*)&u3);
        __half2 p45 = __hadd2(*(__half2*)&u4, *(__half2*)&u5);
        __half2 p67 = __hadd2(*(__half2*)&u6, *(__half2*)&u7);
        __half2 p03 = __hadd2(p01, p23);
        __half2 p47 = __hadd2(p45, p67);
        float2 f0 = __half22float2(p03), f1 = __half22float2(p47);
        acc.x += f0.x + f1.x;
        acc.y += f0.y + f1.y;
    }
    for (; t + 2 <= end; t += 2) {
        int s0 = __ldg(&g_col[t + 0]);
        int s1 = __ldg(&g_col[t + 1]);
        unsigned u0 = ((const unsigned*)(h + (size_t)s0 * 64))[lane];
        unsigned u1 = ((const unsigned*)(h + (size_t)s1 * 64))[lane];
        __half2 p01 = __hadd2(*(__half2*)&u0, *(__half2*)&u1);
        float2 f = __half22float2(p01);
        acc.x += f.x; acc.y += f.y;
    }
    if (t < end) {
        int s = __ldg(&g_col[t]);
        unsigned u = ((const unsigned*)(h + (size_t)s * 64))[lane];
        float2 f = __half22float2(*(__half2*)&u);
        acc.x += f.x; acc.y += f.y;
    }
    const float inv = g_inv_deg[node];
    float2 b = ((const float2*)bias)[lane];
    acc.x = acc.x * inv + b.x;
    acc.y = acc.y * inv + b.y;
    ((float2*)(out + (size_t)node * 64))[lane] = acc;
}

// ---------------- persistent GEMM1: h1 = relu(A@W1+b1) -> fp16 ---------------
__global__ void __launch_bounds__(256, 3)
mma_gemm1(const __half* __restrict__ A, const uint2* __restrict__ B,
          const float* __restrict__ bias, __half* __restrict__ C16) {
    constexpr int BM = 64, BN = 128;
    constexpr int NF = 16, NFW = 8;
    constexpr int A_BYTES = BM * 256;
    constexpr int B_U2 = 8 * NF * 32;

    extern __shared__ __align__(1024) char sm[];
    uint2* Bs = (uint2*)(sm + A_BYTES);
    float* bias_s = (float*)(sm + A_BYTES + B_U2 * 8);

    const int tid = threadIdx.x;
    const uint32_t sb = smem_u32(sm);

    {
        uint4* d4 = (uint4*)Bs;
        const uint4* s4 = (const uint4*)B;
        for (int i = tid; i < B_U2 / 2; i += 256) d4[i] = s4[i];
        if (tid < BN) bias_s[tid] = bias[tid];
    }

    const int warp = tid >> 5, lane = tid & 31;
    const int wn = warp >> 2, wm = warp & 3;
    const int r = wm * 16 + (lane & 15);
    const int arow = r * 256;
    const int arx = r & 7;
    const int chi = lane >> 4;

    for (int mtile = blockIdx.x; mtile < NTILES; mtile += gridDim.x) {
        const int mblock = mtile * BM;
        __syncthreads();
        for (int i = tid; i < BM * 16; i += 256) {
            int row = i >> 4, c = i & 15;
            int grow = mblock + row;
            uint4 v = make_uint4(0, 0, 0, 0);
            if (grow < N_NODES) v = ((const uint4*)(A + (size_t)grow * 128))[c];
            *(uint4*)(sm + row * 256 + ((c ^ (row & 7)) << 4)) = v;
        }
        __syncthreads();

        float acc[NFW][4];
#pragma unroll
        for (int nf = 0; nf < NFW; nf++)
#pragma unroll
            for (int j = 0; j < 4; j++) acc[nf][j] = 0.f;

#pragma unroll
        for (int ks = 0; ks < 8; ks++) {
            uint32_t a[4];
            ldmatrix_x4(a, sb + arow + ((((ks << 1) | chi) ^ arx) << 4));
            uint2 b[NFW];
#pragma unroll
            for (int nf = 0; nf < NFW; nf++)
                b[nf] = Bs[(ks * NF + wn * NFW + nf) * 32 + lane];
#pragma unroll
            for (int nf = 0; nf < NFW; nf++) mma_f16(acc[nf], a, b[nf]);
        }

        const int row0 = mblock + wm * 16 + (lane >> 2);
#pragma unroll
        for (int nf = 0; nf < NFW; nf++) {
            int n0 = (wn * NFW + nf) * 8 + 2 * (lane & 3);
            float b0 = bias_s[n0], b1 = bias_s[n0 + 1];
            unsigned p0 = pack_h2(fmaxf(acc[nf][0] + b0, 0.f), fmaxf(acc[nf][1] + b1, 0.f));
            unsigned p1 = pack_h2(fmaxf(acc[nf][2] + b0, 0.f), fmaxf(acc[nf][3] + b1, 0.f));
            if (row0 < N_NODES)
                *(unsigned*)(C16 + (size_t)row0 * BN + n0) = p0;
            if (row0 + 8 < N_NODES)
                *(unsigned*)(C16 + (size_t)(row0 + 8) * BN + n0) = p1;
        }
    }
}

// ---------------- persistent fused GEMM2+GEMM3 (fp16 single-term) ------------
__global__ void __launch_bounds__(256, 3)
mma_gemm23(const __half* __restrict__ A,
           const uint2* __restrict__ B2, const uint2* __restrict__ B3,
           const float* __restrict__ bias2, __half* __restrict__ Y16) {
    constexpr int BM = 64;
    constexpr int A_BYTES = BM * 256;
    constexpr int B2_U2 = 8 * 16 * 32;
    constexpr int B3_U2 = 8 * 8 * 32;

    extern __shared__ __align__(1024) char sm[];
    uint2* Bs2 = (uint2*)(sm + A_BYTES);
    uint2* Bs3 = (uint2*)(sm + A_BYTES + B2_U2 * 8);
    float* bias_s = (float*)(sm + A_BYTES + B2_U2 * 8 + B3_U2 * 8);

    const int tid = threadIdx.x;
    const uint32_t sb = smem_u32(sm);

    {
        uint4* d2 = (uint4*)Bs2;
        const uint4* s2 = (const uint4*)B2;
        for (int i = tid; i < B2_U2 / 2; i += 256) d2[i] = s2[i];
        uint4* d3 = (uint4*)Bs3;
        const uint4* s3 = (const uint4*)B3;
        for (int i = tid; i < B3_U2 / 2; i += 256) d3[i] = s3[i];
        if (tid < 128) bias_s[tid] = bias2[tid];
    }

    const int warp = tid >> 5, lane = tid & 31;
    const int wn = warp >> 2, wm = warp & 3;
    const int r = wm * 16 + (lane & 15);
    const int arow = r * 256;
    const int arx = r & 7;
    const int chi = lane >> 4;
    const int lr0 = wm * 16 + (lane >> 2);

    for (int mtile = blockIdx.x; mtile < NTILES; mtile += gridDim.x) {
        const int mblock = mtile * BM;
        __syncthreads();
        for (int i = tid; i < BM * 16; i += 256) {
            int row = i >> 4, c = i & 15;
            int grow = mblock + row;
            uint4 v = make_uint4(0, 0, 0, 0);
            if (grow < N_NODES) v = ((const uint4*)(A + (size_t)grow * 128))[c];
            *(uint4*)(sm + row * 256 + ((c ^ (row & 7)) << 4)) = v;
        }
        __syncthreads();

        // ---- mainloop 1: A @ W2 ----
        float acc[8][4];
#pragma unroll
        for (int nf = 0; nf < 8; nf++)
#pragma unroll
            for (int j = 0; j < 4; j++) acc[nf][j] = 0.f;

#pragma unroll
        for (int ks = 0; ks < 8; ks++) {
            uint32_t a[4];
            ldmatrix_x4(a, sb + arow + ((((ks << 1) | chi) ^ arx) << 4));
            uint2 b[8];
#pragma unroll
            for (int nf = 0; nf < 8; nf++)
                b[nf] = Bs2[(ks * 16 + wn * 8 + nf) * 32 + lane];
#pragma unroll
            for (int nf = 0; nf < 8; nf++) mma_f16(acc[nf], a, b[nf]);
        }
        __syncthreads();  // all A reads done before overwrite

        // ---- h2 = relu(acc + b2) -> fp16 back into A smem ----
#pragma unroll
        for (int nf = 0; nf < 8; nf++) {
            int n0 = (wn * 8 + nf) * 8 + 2 * (lane & 3);
            float b0 = bias_s[n0], b1 = bias_s[n0 + 1];
            unsigned p0 = pack_h2(fmaxf(acc[nf][0] + b0, 0.f), fmaxf(acc[nf][1] + b1, 0.f));
            unsigned p1 = pack_h2(fmaxf(acc[nf][2] + b0, 0.f), fmaxf(acc[nf][3] + b1, 0.f));
            *(unsigned*)(sm + a_off(lr0, n0)) = p0;
            *(unsigned*)(sm + a_off(lr0 + 8, n0)) = p1;
        }
        __syncthreads();

        // ---- mainloop 2: h2 @ W3 (BN=64) ----
        float acc2[4][4];
#pragma unroll
        for (int nf = 0; nf < 4; nf++)
#pragma unroll
            for (int j = 0; j < 4; j++) acc2[nf][j] = 0.f;

#pragma unroll
        for (int ks = 0; ks < 8; ks++) {
            uint32_t a[4];
            ldmatrix_x4(a, sb + arow + ((((ks << 1) | chi) ^ arx) << 4));
            uint2 b[4];
#pragma unroll
            for (int nf = 0; nf < 4; nf++)
                b[nf] = Bs3[(ks * 8 + wn * 4 + nf) * 32 + lane];
#pragma unroll
            for (int nf = 0; nf < 4; nf++) mma_f16(acc2[nf], a, b[nf]);
        }

        const int row0 = mblock + lr0;
#pragma unroll
        for (int nf = 0; nf < 4; nf++) {
            int n0 = (wn * 4 + nf) * 8 + 2 * (lane & 3);
            unsigned p0 = pack_h2(acc2[nf][0], acc2[nf][1]);
            unsigned p1 = pack_h2(acc2[nf][2], acc2[nf][3]);
            if (row0 < N_NODES)
                *(unsigned*)(Y16 + (size_t)row0 * 64 + n0) = p0;
            if (row0 + 8 < N_NODES)
                *(unsigned*)(Y16 + (size_t)(row0 + 8) * 64 + n0) = p1;
        }
    }
}

// ---------------- launch ----------------
extern "C" void kernel_launch(void* const* d_in, const int* in_sizes, int n_in,
                              void* d_out, int out_size) {
    const float* features = (const float*)d_in[0];
    const int* src = (const int*)d_in[1];
    const int* dst = (const int*)d_in[2];
    const float* W1 = (const float*)d_in[3];
    const float* b1 = (const float*)d_in[4];
    const float* W2 = (const float*)d_in[5];
    const float* b2 = (const float*)d_in[6];
    const float* W3 = (const float*)d_in[7];
    const float* b3 = (const float*)d_in[8];
    float* out = (float*)d_out;

    void* p;
    cudaGetSymbolAddress(&p, g_F16); __half* F16 = (__half*)p;
    cudaGetSymbolAddress(&p, g_A16); __half* A16 = (__half*)p;
    cudaGetSymbolAddress(&p, g_W1); uint2* W1p = (uint2*)p;
    cudaGetSymbolAddress(&p, g_W2); uint2* W2p = (uint2*)p;
    cudaGetSymbolAddress(&p, g_W3); uint2* W3p = (uint2*)p;

    constexpr int SMEM1  = 64 * 256 + (8 * 16 * 32) * 8 + 512;                     // 49664
    constexpr int SMEM23 = 64 * 256 + (8 * 16 * 32) * 8 + (8 * 8 * 32) * 8 + 512;  // 66048
    cudaFuncSetAttribute(mma_gemm1,
                         cudaFuncAttributeMaxDynamicSharedMemorySize, SMEM1);
    cudaFuncSetAttribute(mma_gemm23,
                         cudaFuncAttributeMaxDynamicSharedMemorySize, SMEM23);

    const int AGG_BLOCKS = (N_NODES * 32 + 255) / 256;
    const int FILLB = (N_EDGES / 2 + 255) / 256;  // 1172

    // #1 degree count (+slot) + weight prep + features->fp16
    count_cvt_prep_kernel<<<E4B + PREPB + CVTB2, 256>>>(dst, features, W1, W2, W3);
    // #2 fused scan (spin barrier) + deg re-zero
    scanAC_kernel<<<SCAN_BLOCKS, 1024>>>();
    // #3 atomic-free CSR fill
    fill2_kernel<<<FILLB, 256>>>(src, dst);

    // Layer 1 (#4 = profiled slot: aggregate)
    aggregate_f16_kernel<<<AGG_BLOCKS, 256>>>(F16, A16);
    mma_gemm1<<<148 * 3, 256, SMEM1>>>(A16, W1p, b1, F16);
    // Layer 2 + dense part of layer 3 (fused)
    aggregate_f16_kernel<<<AGG_BLOCKS, 256>>>(F16, A16);
    mma_gemm23<<<148 * 3, 256, SMEM23>>>(A16, W2p, W3p, b2, F16);
    // Layer 3 tail: aggregate + bias
    aggregate64_kernel<<<AGG_BLOCKS, 256>>>(F16, b3, out);
}